// round 10
// baseline (speedup 1.0000x reference)
#include <cuda_runtime.h>
#include <cuda_bf16.h>
#include <math.h>
#include <stdint.h>

#define T_ 16
#define HW_ 1024
#define M_ 256
#define D_ 768
#define H_ 8
#define HD_ 96
#define SCALE_F 0.1020620726159658f  /* 1/sqrt(96) */

typedef __nv_bfloat16 bf16;
typedef __nv_bfloat162 bf162;

// ---------------- scratch (static device globals; no allocation) ----------------
__device__ __align__(256) bf16 h_feat[(size_t)T_ * HW_ * D_];
__device__ __align__(256) bf16 h_fp  [(size_t)T_ * HW_ * D_];   // featplus
__device__ __align__(256) bf16 h_fpe [(size_t)T_ * HW_ * D_];
__device__ __align__(256) bf16 h_kb  [(size_t)T_ * HW_ * D_];   // K_ln
__device__ __align__(256) bf16 h_vb  [(size_t)T_ * HW_ * D_];   // V
__device__ __align__(256) bf16 h_big0[(size_t)T_ * HW_ * D_];   // K pre-LN
__device__ __align__(256) bf16 h_big1[(size_t)T_ * HW_ * D_];   // Q2 pre-LN
__device__ __align__(256) bf16 h_q2  [(size_t)T_ * HW_ * D_];   // Q2_ln
__device__ __align__(256) bf16 h_upd [(size_t)T_ * HW_ * D_];   // flash2 out
__device__ __align__(256) bf16 h_tpe [(size_t)T_ * M_ * D_];
__device__ __align__(256) bf16 h_qb  [(size_t)T_ * M_ * D_];    // Q_ln
__device__ __align__(256) bf16 h_k2  [(size_t)T_ * M_ * D_];    // K2_ln
__device__ __align__(256) bf16 h_qk2 [(size_t)T_ * M_ * 2 * D_]; // Q|K2 pre-LN (ldc=1536)
__device__ __align__(256) bf16 h_sh  [(size_t)T_ * M_ * D_];    // sampled-heads
__device__ __align__(256) bf16 h_v2  [(size_t)T_ * M_ * D_];    // V2
__device__ __align__(256) bf16 h_W[8][D_ * D_];
__device__ __align__(256) bf16 h_wt [D_ * D_];                   // Wo_s^T (bf16)
__device__ __align__(256) bf16 h_wc [D_ * D_];                   // Wc = Wv_p @ Wo_s

// ---------------- ptx helpers ----------------
__device__ __forceinline__ unsigned cvta_s(const void* p) {
    return (unsigned)__cvta_generic_to_shared(p);
}
#define CP16(dst, src) asm volatile("cp.async.cg.shared.global [%0], [%1], 16;" :: "r"(dst), "l"(src))
#define CPC() asm volatile("cp.async.commit_group;")
#define CPW(n) asm volatile("cp.async.wait_group %0;" :: "n"(n))

__device__ __forceinline__ void ldsm4(unsigned a, unsigned& r0, unsigned& r1, unsigned& r2, unsigned& r3) {
    asm volatile("ldmatrix.sync.aligned.m8n8.x4.shared.b16 {%0,%1,%2,%3}, [%4];"
                 : "=r"(r0), "=r"(r1), "=r"(r2), "=r"(r3) : "r"(a));
}
__device__ __forceinline__ void ldsm4t(unsigned a, unsigned& r0, unsigned& r1, unsigned& r2, unsigned& r3) {
    asm volatile("ldmatrix.sync.aligned.m8n8.x4.trans.shared.b16 {%0,%1,%2,%3}, [%4];"
                 : "=r"(r0), "=r"(r1), "=r"(r2), "=r"(r3) : "r"(a));
}
__device__ __forceinline__ void mma_bf16(float* c,
    unsigned a0, unsigned a1, unsigned a2, unsigned a3, unsigned b0, unsigned b1) {
    asm volatile(
        "mma.sync.aligned.m16n8k16.row.col.f32.bf16.bf16.f32 "
        "{%0,%1,%2,%3},{%4,%5,%6,%7},{%8,%9},{%0,%1,%2,%3};"
        : "+f"(c[0]), "+f"(c[1]), "+f"(c[2]), "+f"(c[3])
        : "r"(a0), "r"(a1), "r"(a2), "r"(a3), "r"(b0), "r"(b1));
}
__device__ __forceinline__ unsigned packbf(float x, float y) {
    bf162 v = __floats2bfloat162_rn(x, y);
    return *reinterpret_cast<unsigned*>(&v);
}
// swizzled bf16-unit offset in a [rows][32] bf16 tile (flash path)
__device__ __forceinline__ unsigned swz(int row, int g) {
    return ((row >> 1) << 6) | (((((row & 1) << 2) | g) ^ ((row >> 1) & 7)) << 3);
}
// swizzled BYTE offset in a [rows][64] bf16 tile (128B rows; gemm BK=64 path); g = 16B chunk 0..7
__device__ __forceinline__ unsigned swb(int row, int g) {
    return (unsigned)((row << 7) | (((g ^ (row & 7)) & 7) << 4));
}

// ---------------- conversions ----------------
__global__ __launch_bounds__(256) void cvt3(const float* __restrict__ f, const float* __restrict__ pe,
                                            bf16* __restrict__ feat, bf16* __restrict__ fpeh,
                                            bf16* __restrict__ fph, int n4) {
    int i = blockIdx.x * 256 + threadIdx.x;
    if (i < n4) {
        float4 x = ((const float4*)f)[i];
        float4 y = ((const float4*)pe)[i];
        ((bf162*)feat)[2 * i]     = __floats2bfloat162_rn(x.x, x.y);
        ((bf162*)feat)[2 * i + 1] = __floats2bfloat162_rn(x.z, x.w);
        ((bf162*)fpeh)[2 * i]     = __floats2bfloat162_rn(y.x, y.y);
        ((bf162*)fpeh)[2 * i + 1] = __floats2bfloat162_rn(y.z, y.w);
        ((bf162*)fph)[2 * i]      = __floats2bfloat162_rn(x.x + y.x, x.y + y.y);
        ((bf162*)fph)[2 * i + 1]  = __floats2bfloat162_rn(x.z + y.z, x.w + y.w);
    }
}
__global__ __launch_bounds__(256) void cvt4(const float* __restrict__ s, bf16* __restrict__ d, int n4) {
    int i = blockIdx.x * 256 + threadIdx.x;
    if (i < n4) {
        float4 v = ((const float4*)s)[i];
        ((bf162*)d)[2 * i]     = __floats2bfloat162_rn(v.x, v.y);
        ((bf162*)d)[2 * i + 1] = __floats2bfloat162_rn(v.z, v.w);
    }
}
struct WP { const float* p[8]; };
__global__ __launch_bounds__(256) void cvtw(WP wp, bf16* __restrict__ dst) {
    int wi = blockIdx.y;
    const float* s = wp.p[wi];
    bf16* d = dst + (size_t)wi * (D_ * D_);
    int i = blockIdx.x * 256 + threadIdx.x;
    float4 v = ((const float4*)s)[i];
    ((bf162*)d)[2 * i]     = __floats2bfloat162_rn(v.x, v.y);
    ((bf162*)d)[2 * i + 1] = __floats2bfloat162_rn(v.z, v.w);
}
// transpose 768x768 fp32 -> bf16 (D[j,k] = S[k,j])
__global__ __launch_bounds__(256) void twt(const float* __restrict__ S, bf16* __restrict__ D) {
    __shared__ float tile[32][33];
    int bx = blockIdx.x * 32, by = blockIdx.y * 32;
    int tx = threadIdx.x & 31, ty = threadIdx.x >> 5;   // 32 x 8
#pragma unroll
    for (int i = 0; i < 32; i += 8)
        tile[ty + i][tx] = S[(size_t)(by + ty + i) * D_ + bx + tx];
    __syncthreads();
#pragma unroll
    for (int i = 0; i < 32; i += 8)
        D[(size_t)(bx + ty + i) * D_ + by + tx] = __float2bfloat16(tile[tx][ty + i]);
}

// ---------------- LayerNorm: bf16 in (stride ldx) -> bf16 out (stride 768) -------
__global__ __launch_bounds__(256) void ln_bh(const bf16* __restrict__ X, int ldx,
                                             const float* __restrict__ g, bf16* __restrict__ Y) {
    const bf16* row = X + (size_t)blockIdx.x * ldx;
    bf16* orow = Y + (size_t)blockIdx.x * D_;
    int tid = threadIdx.x, lane = tid & 31, w = tid >> 5;
    float v0 = __bfloat162float(row[tid]);
    float v1 = __bfloat162float(row[tid + 256]);
    float v2 = __bfloat162float(row[tid + 512]);
    float s = v0 + v1 + v2;
    float q = v0 * v0 + v1 * v1 + v2 * v2;
#pragma unroll
    for (int o = 16; o; o >>= 1) {
        s += __shfl_xor_sync(~0u, s, o);
        q += __shfl_xor_sync(~0u, q, o);
    }
    __shared__ float ps[8], pq[8], bc[2];
    if (lane == 0) { ps[w] = s; pq[w] = q; }
    __syncthreads();
    if (tid == 0) {
        float ts = 0.0f, tq = 0.0f;
#pragma unroll
        for (int i = 0; i < 8; i++) { ts += ps[i]; tq += pq[i]; }
        float mean = ts * (1.0f / 768.0f);
        float var = tq * (1.0f / 768.0f) - mean * mean;
        bc[0] = mean;
        bc[1] = rsqrtf(var + 1e-6f);
    }
    __syncthreads();
    float mean = bc[0], inv = bc[1];
    orow[tid]       = __float2bfloat16((v0 - mean) * inv * g[tid]);
    orow[tid + 256] = __float2bfloat16((v1 - mean) * inv * g[tid + 256]);
    orow[tid + 512] = __float2bfloat16((v2 - mean) * inv * g[tid + 512]);
}

// ---------------- dense GEMM: C[R,N] = A[R,768] @ W[N,768]^T (out stride ldc) ----
// BK=64, 3-stage cp.async (96KB smem), one barrier per 64-wide k-step.
__global__ __launch_bounds__(256) void gemm_h(
    const bf16* __restrict__ A, const bf16* __restrict__ W,
    const float* __restrict__ addsrc, float* __restrict__ Cf, bf16* __restrict__ Ch,
    int ldc)
{
    extern __shared__ bf16 sm[];          // 3 stages x (A 16KB | W 16KB)
    const int tid = threadIdx.x, lane = tid & 31, warp = tid >> 5;
    const int wm = warp & 3, wn = warp >> 2;
    const int bm = blockIdx.y * 128, bn = blockIdx.x * 128;
    const unsigned base = cvta_s(sm);

    // staging map: 4 x 16B chunks per operand per thread (128x64 bf16 tiles)
    unsigned sw_[4];
    const bf16* Ap[4];
    const bf16* Wp[4];
#pragma unroll
    for (int j = 0; j < 4; j++) {
        int idx = tid + j * 256;
        int row = idx >> 3, c16 = idx & 7;
        sw_[j] = swb(row, c16);
        Ap[j] = A + (size_t)(bm + row) * D_ + c16 * 8;
        Wp[j] = W + (size_t)(bn + row) * D_ + c16 * 8;
    }

    float c[2][8][4] = {};

    // prologue: stages 0,1
#pragma unroll
    for (int s = 0; s < 2; s++) {
        unsigned o = s * 32768u;
        int k0 = s * 64;
#pragma unroll
        for (int j = 0; j < 4; j++) {
            CP16(base + o + sw_[j], Ap[j] + k0);
            CP16(base + o + 16384u + sw_[j], Wp[j] + k0);
        }
        CPC();
    }

    const int ITERS = D_ / 64;  // 12
    const int rlow = lane & 15, khalf = lane >> 4;
    for (int it = 0; it < ITERS; ++it) {
        CPW(1);
        __syncthreads();
        if (it + 2 < ITERS) {
            int k0 = (it + 2) * 64;
            unsigned o = (unsigned)((it + 2) % 3) * 32768u;
#pragma unroll
            for (int j = 0; j < 4; j++) {
                CP16(base + o + sw_[j], Ap[j] + k0);
                CP16(base + o + 16384u + sw_[j], Wp[j] + k0);
            }
        }
        CPC();
        unsigned ab = base + (unsigned)(it % 3) * 32768u, wb = ab + 16384u;
#pragma unroll
        for (int kk = 0; kk < 64; kk += 16) {
            int g = (kk >> 3) + khalf;   // 16B chunk 0..7
            unsigned a[2][4], bfr[4][4];
#pragma unroll
            for (int mt = 0; mt < 2; mt++) {
                int row = wm * 32 + mt * 16 + rlow;
                ldsm4(ab + swb(row, g), a[mt][0], a[mt][1], a[mt][2], a[mt][3]);
            }
#pragma unroll
            for (int bt = 0; bt < 4; bt++) {
                int row = wn * 64 + bt * 16 + rlow;
                ldsm4(wb + swb(row, g), bfr[bt][0], bfr[bt][1], bfr[bt][2], bfr[bt][3]);
            }
#pragma unroll
            for (int mt = 0; mt < 2; mt++)
#pragma unroll
                for (int nt = 0; nt < 8; nt++) {
                    int bt = nt >> 1, hi = nt & 1;
                    mma_bf16(c[mt][nt], a[mt][0], a[mt][1], a[mt][2], a[mt][3],
                             bfr[bt][hi ? 1 : 0], bfr[bt][hi ? 3 : 2]);
                }
        }
    }

    const int ml = lane >> 2, nl = 2 * (lane & 3);
#pragma unroll
    for (int mt = 0; mt < 2; mt++) {
        int m0 = bm + wm * 32 + mt * 16 + ml;
#pragma unroll
        for (int nt = 0; nt < 8; nt++) {
            int n0 = bn + wn * 64 + nt * 8 + nl;
            size_t o0 = (size_t)m0 * ldc + n0, o1 = o0 + (size_t)8 * ldc;
            float x0 = c[mt][nt][0], x1 = c[mt][nt][1];
            float y0 = c[mt][nt][2], y1 = c[mt][nt][3];
            if (addsrc) {
                float2 s0 = *(const float2*)(addsrc + o0);
                float2 s1 = *(const float2*)(addsrc + o1);
                x0 += s0.x; x1 += s0.y; y0 += s1.x; y1 += s1.y;
            }
            if (Cf) {
                *(float2*)(Cf + o0) = make_float2(x0, x1);
                *(float2*)(Cf + o1) = make_float2(y0, y1);
            }
            if (Ch) {
                *(bf162*)(Ch + o0) = __floats2bfloat162_rn(x0, x1);
                *(bf162*)(Ch + o1) = __floats2bfloat162_rn(y0, y1);
            }
        }
    }
}

// ---------------- fused flash attention (R5 proven, unchanged) ----------------
template<int MQ, int KN, bool QPT, bool KPT>
__global__ __launch_bounds__(128) void flash_h(
    const bf16* __restrict__ Q, const bf16* __restrict__ K,
    const bf16* __restrict__ V, bf16* __restrict__ O,
    const float* __restrict__ qpos, const float* __restrict__ kpos)
{
    constexpr int ITERS = KN / 64;
    extern __shared__ char smem[];
    unsigned qU  = cvta_s(smem);
    unsigned kU  = qU + 12288;
    unsigned vU  = qU + 36864;
    unsigned kpU = qU + 63488;
    float2* sKP = (float2*)(smem + 63488);

    const int z = blockIdx.y, t = z >> 3, h = z & 7;
    const int bm = blockIdx.x * 64;
    const bf16* Qb = Q + (size_t)t * MQ * D_ + h * HD_;
    const bf16* Kb = K + (size_t)t * KN * D_ + h * HD_;
    const bf16* Vb = V + (size_t)t * KN * D_ + h * HD_;
    bf16* Ob = O + (size_t)t * MQ * D_ + h * HD_;
    const float* qp = qpos + (QPT ? (size_t)t * MQ * 2 : 0);
    const float* kp = kpos + (KPT ? (size_t)t * KN * 2 : 0);

    const int tid = threadIdx.x, lane = tid & 31, w = tid >> 5;
    const int gq = lane >> 2, tg = lane & 3;
    const int rlow = lane & 15, khalf = lane >> 4;

    int lrow[6], lg[6];
    unsigned kdst[6], vdst[6];
    size_t soff[6];
#pragma unroll
    for (int i = 0; i < 6; i++) {
        int idx = tid + i * 128;
        lrow[i] = idx / 12; lg[i] = idx % 12;
        kdst[i] = ((lg[i] >> 2) * 4096) + (swz(lrow[i], lg[i] & 3) << 1);
        vdst[i] = lrow[i] * 208 + lg[i] * 16;
        soff[i] = (size_t)lrow[i] * D_ + lg[i] * 8;
    }

#pragma unroll
    for (int i = 0; i < 6; i++) {
        CP16(qU + kdst[i], Qb + (size_t)bm * D_ + soff[i]);
        CP16(kU + kdst[i], Kb + soff[i]);
        CP16(vU + vdst[i], Vb + soff[i]);
    }
    if (tid < 32) CP16(kpU + tid * 16, (const char*)kp + tid * 16);
    CPC();

    float2 q0 = *(const float2*)(qp + 2 * (bm + w * 16 + gq));
    float2 q1 = *(const float2*)(qp + 2 * (bm + w * 16 + gq + 8));

    float m0 = -1e30f, m1 = -1e30f, l0 = 0.0f, l1 = 0.0f;
    float o[12][4] = {};
    unsigned qa[6][4];

    for (int it = 0; it < ITERS; ++it) {
        int buf = it & 1;
        if (it + 1 < ITERS) {
            int kb = (it + 1) * 64;
            unsigned ok = (buf ^ 1) * 12288u, ov = (buf ^ 1) * 13312u;
            size_t sb = (size_t)kb * D_;
#pragma unroll
            for (int i = 0; i < 6; i++) {
                CP16(kU + ok + kdst[i], Kb + sb + soff[i]);
                CP16(vU + ov + vdst[i], Vb + sb + soff[i]);
            }
            if (tid < 32) CP16(kpU + (buf ^ 1) * 512 + tid * 16, (const char*)kp + (size_t)kb * 8 + tid * 16);
            CPC(); CPW(1);
        } else CPW(0);
        __syncthreads();

        if (it == 0) {
#pragma unroll
            for (int ks = 0; ks < 6; ks++) {
                int kc = ks >> 1, g = ((ks & 1) << 1) + khalf;
                ldsm4(qU + kc * 4096 + (swz(w * 16 + rlow, g) << 1),
                      qa[ks][0], qa[ks][1], qa[ks][2], qa[ks][3]);
            }
        }

        unsigned kbase = kU + buf * 12288u, vbase = vU + buf * 13312u;
        float2* kpb = sKP + buf * 64;

        float s[8][4] = {};
#pragma unroll
        for (int ks = 0; ks < 6; ks++) {
            int kc = ks >> 1, g = ((ks & 1) << 1) + khalf;
            unsigned bfr[4][4];
#pragma unroll
            for (int rg = 0; rg < 4; rg++)
                ldsm4(kbase + kc * 4096 + (swz(rg * 16 + rlow, g) << 1),
                      bfr[rg][0], bfr[rg][1], bfr[rg][2], bfr[rg][3]);
#pragma unroll
            for (int rg = 0; rg < 4; rg++) {
                mma_bf16(s[2 * rg],     qa[ks][0], qa[ks][1], qa[ks][2], qa[ks][3], bfr[rg][0], bfr[rg][2]);
                mma_bf16(s[2 * rg + 1], qa[ks][0], qa[ks][1], qa[ks][2], qa[ks][3], bfr[rg][1], bfr[rg][3]);
            }
        }

        float rm0 = -1e30f, rm1 = -1e30f;
#pragma unroll
        for (int j = 0; j < 8; j++) {
            float2 kp0 = kpb[8 * j + 2 * tg];
            float2 kp1 = kpb[8 * j + 2 * tg + 1];
            float dx, dy;
            dx = q0.x - kp0.x; dy = q0.y - kp0.y;
            s[j][0] = s[j][0] * SCALE_F - 2.0f * (dx * dx + dy * dy);
            dx = q0.x - kp1.x; dy = q0.y - kp1.y;
            s[j][1] = s[j][1] * SCALE_F - 2.0f * (dx * dx + dy * dy);
            dx = q1.x - kp0.x; dy = q1.y - kp0.y;
            s[j][2] = s[j][2] * SCALE_F - 2.0f * (dx * dx + dy * dy);
            dx = q1.x - kp1.x; dy = q1.y - kp1.y;
            s[j][3] = s[j][3] * SCALE_F - 2.0f * (dx * dx + dy * dy);
            rm0 = fmaxf(rm0, fmaxf(s[j][0], s[j][1]));
            rm1 = fmaxf(rm1, fmaxf(s[j][2], s[j][3]));
        }
        rm0 = fmaxf(rm0, __shfl_xor_sync(~0u, rm0, 1));
        rm0 = fmaxf(rm0, __shfl_xor_sync(~0u, rm0, 2));
        rm1 = fmaxf(rm1, __shfl_xor_sync(~0u, rm1, 1));
        rm1 = fmaxf(rm1, __shfl_xor_sync(~0u, rm1, 2));

        float m0n = fmaxf(m0, rm0), m1n = fmaxf(m1, rm1);
        float sc0 = __expf(m0 - m0n), sc1 = __expf(m1 - m1n);
        m0 = m0n; m1 = m1n;
        l0 *= sc0; l1 *= sc1;
#pragma unroll
        for (int j = 0; j < 8; j++) {
            s[j][0] = __expf(s[j][0] - m0n);
            s[j][1] = __expf(s[j][1] - m0n);
            s[j][2] = __expf(s[j][2] - m1n);
            s[j][3] = __expf(s[j][3] - m1n);
            l0 += s[j][0] + s[j][1];
            l1 += s[j][2] + s[j][3];
        }
#pragma unroll
        for (int nt = 0; nt < 12; nt++) {
            o[nt][0] *= sc0; o[nt][1] *= sc0;
            o[nt][2] *= sc1; o[nt][3] *= sc1;
        }

        unsigned pa[4][4];
#pragma unroll
        for (int kk = 0; kk < 4; kk++) {
            pa[kk][0] = packbf(s[2 * kk][0],     s[2 * kk][1]);
            pa[kk][1] = packbf(s[2 * kk][2],     s[2 * kk][3]);
            pa[kk][2] = packbf(s[2 * kk + 1][0], s[2 * kk + 1][1]);
            pa[kk][3] = packbf(s[2 * kk + 1][2], s[2 * kk + 1][3]);
        }

#pragma unroll
        for (int kk = 0; kk < 4; kk++) {
#pragma unroll
            for (int p = 0; p < 6; p++) {
                unsigned baddr = vbase + (kk * 16 + rlow) * 208 + (p * 16 + khalf * 8) * 2;
                unsigned b0, b1, b2, b3;
                ldsm4t(baddr, b0, b1, b2, b3);
                mma_bf16(o[2 * p],     pa[kk][0], pa[kk][1], pa[kk][2], pa[kk][3], b0, b1);
                mma_bf16(o[2 * p + 1], pa[kk][0], pa[kk][1], pa[kk][2], pa[kk][3], b2, b3);
            }
        }
        __syncthreads();
    }

    l0 += __shfl_xor_sync(~0u, l0, 1); l0 += __shfl_xor_sync(~0u, l0, 2);
    l1 += __shfl_xor_sync(~0u, l1, 1); l1 += __shfl_xor_sync(~0u, l1, 2);
    float inv0 = 1.0f / l0, inv1 = 1.0f / l1;

    int mrow = bm + w * 16 + gq;
#pragma unroll
    for (int nt = 0; nt < 12; nt++) {
        int n0 = nt * 8 + 2 * tg;
        *(bf162*)(Ob + (size_t)mrow * D_ + n0) =
            __floats2bfloat162_rn(o[nt][0] * inv0, o[nt][1] * inv0);
        *(bf162*)(Ob + (size_t)(mrow + 8) * D_ + n0) =
            __floats2bfloat162_rn(o[nt][2] * inv1, o[nt][3] * inv1);
    }
}

// ---------------- persistent stream/event handles (created once, reused) --------
struct Ctx {
    cudaStream_t s1, s2;
    cudaEvent_t eStart, eW, e3, eQ, eQ2, eV, eK2, eWc;
    Ctx() {
        cudaStreamCreateWithFlags(&s1, cudaStreamNonBlocking);
        cudaStreamCreateWithFlags(&s2, cudaStreamNonBlocking);
        cudaEventCreateWithFlags(&eStart, cudaEventDisableTiming);
        cudaEventCreateWithFlags(&eW, cudaEventDisableTiming);
        cudaEventCreateWithFlags(&e3, cudaEventDisableTiming);
        cudaEventCreateWithFlags(&eQ, cudaEventDisableTiming);
        cudaEventCreateWithFlags(&eQ2, cudaEventDisableTiming);
        cudaEventCreateWithFlags(&eV, cudaEventDisableTiming);
        cudaEventCreateWithFlags(&eK2, cudaEventDisableTiming);
        cudaEventCreateWithFlags(&eWc, cudaEventDisableTiming);
    }
};

// =================================================================================
extern "C" void kernel_launch(void* const* d_in, const int* in_sizes, int n_in,
                              void* d_out, int out_size)
{
    static Ctx ctx;   // one-time creation on first call (pre-baseline)

    const float* features = (const float*)d_in[0];
    const float* tracks   = (const float*)d_in[1];
    const float* fpos     = (const float*)d_in[2];
    const float* tpe      = (const float*)d_in[3];
    const float* fpe      = (const float*)d_in[4];
    // weight slots (converted bf16): 0=Wq_s, 1=Wk_p (adjacent for fused QK2 GEMM),
    // 2=Wk_s, 3=Wv_s, 4=Wq_p, 5=Wv_p, 6=Wout_p, 7=Wo_s
    WP wp;
    wp.p[0] = (const float*)d_in[5];   // Wq_s
    wp.p[1] = (const float*)d_in[12];  // Wk_p
    wp.p[2] = (const float*)d_in[6];   // Wk_s
    wp.p[3] = (const float*)d_in[7];   // Wv_s
    wp.p[4] = (const float*)d_in[11];  // Wq_p
    wp.p[5] = (const float*)d_in[13];  // Wv_p
    wp.p[6] = (const float*)d_in[16];  // Wout_p
    wp.p[7] = (const float*)d_in[10];  // Wo_s
    const float* qg_s = (const float*)d_in[8];
    const float* kg_s = (const float*)d_in[9];
    const float* qg_p = (const float*)d_in[14];
    const float* kg_p = (const float*)d_in[15];
    float* out = (float*)d_out;

    bf16 *feat_h, *fp_h, *fpe_h, *kb_h, *vb_h, *big0_h, *big1_h, *q2_h, *upd_h;
    bf16 *tpe_h, *qb_h, *k2_h, *qk2_h, *sh_h, *v2_h, *w_h, *wt_h, *wc_h;
    cudaGetSymbolAddress((void**)&feat_h, h_feat);
    cudaGetSymbolAddress((void**)&fp_h,   h_fp);
    cudaGetSymbolAddress((void**)&fpe_h,  h_fpe);
    cudaGetSymbolAddress((void**)&kb_h,   h_kb);
    cudaGetSymbolAddress((void**)&vb_h,   h_vb);
    cudaGetSymbolAddress((void**)&big0_h, h_big0);
    cudaGetSymbolAddress((void**)&big1_h, h_big1);
    cudaGetSymbolAddress((void**)&q2_h,   h_q2);
    cudaGetSymbolAddress((void**)&upd_h,  h_upd);
    cudaGetSymbolAddress((void**)&tpe_h,  h_tpe);
    cudaGetSymbolAddress((void**)&qb_h,   h_qb);
    cudaGetSymbolAddress((void**)&k2_h,   h_k2);
    cudaGetSymbolAddress((void**)&qk2_h,  h_qk2);
    cudaGetSymbolAddress((void**)&sh_h,   h_sh);
    cudaGetSymbolAddress((void**)&v2_h,   h_v2);
    cudaGetSymbolAddress((void**)&w_h,    h_W);
    cudaGetSymbolAddress((void**)&wt_h,   h_wt);
    cudaGetSymbolAddress((void**)&wc_h,   h_wc);

    const int NBIG = T_ * HW_ * D_;  // 12,582,912
    const int NSM  = T_ * M_ * D_;   // 3,145,728
    const int NW   = D_ * D_;        // 589,824

    const int GSMEM = 98304;   // 3 stages x 32KB
    cudaFuncSetAttribute(gemm_h, cudaFuncAttributeMaxDynamicSharedMemorySize, GSMEM);
    const int FSMEM = 64512;
    cudaFuncSetAttribute(flash_h<M_, HW_, true, false>,
                         cudaFuncAttributeMaxDynamicSharedMemorySize, FSMEM);
    cudaFuncSetAttribute(flash_h<HW_, M_, false, true>,
                         cudaFuncAttributeMaxDynamicSharedMemorySize, FSMEM);

    cudaStream_t s1 = ctx.s1, s2 = ctx.s2;

    dim3 gBig(6, 128);    // N=768, M=16384
    dim3 gSm(6, 32);      // N=768, M=4096
    dim3 gQK2(12, 32);    // N=1536, M=4096 (fused Q|K2)
    dim3 gW(6, 6);        // 768x768

    // fork s1/s2 from the capturing (legacy) stream
    cudaEventRecord(ctx.eStart, 0);
    cudaStreamWaitEvent(s1, ctx.eStart, 0);
    cudaStreamWaitEvent(s2, ctx.eStart, 0);

    // s2: weight conversion, WoT transpose, Wc = Wv_p @ Wo_s, then V chain
    cvtw<<<dim3(NW / 1024, 8), 256, 0, s2>>>(wp, w_h);
    cudaEventRecord(ctx.eW, s2);
    twt<<<dim3(24, 24), 256, 0, s2>>>(wp.p[7], wt_h);                                          // Wo_s^T
    gemm_h<<<gW, 256, GSMEM, s2>>>(w_h + 5 * (size_t)NW, wt_h, nullptr, nullptr, wc_h, D_);    // Wc
    cudaEventRecord(ctx.eWc, s2);

    // stream 0: big conversions + K chain (critical path)
    cvt3<<<NBIG / 1024, 256>>>(features, fpe, feat_h, fpe_h, fp_h, NBIG / 4);
    cudaEventRecord(ctx.e3, 0);

    // s1: tpe conversion, fused Q|K2 GEMM + LNs, then Q2 chain
    cvt4<<<NSM / 1024, 256, 0, s1>>>(tpe, tpe_h, NSM / 4);
    cudaStreamWaitEvent(s1, ctx.eW, 0);
    gemm_h<<<gQK2, 256, GSMEM, s1>>>(tpe_h, w_h, nullptr, nullptr, qk2_h, 2 * D_);             // Q|K2
    ln_bh<<<T_ * M_, 256, 0, s1>>>(qk2_h, 2 * D_, qg_s, qb_h);                                 // Q_ln
    cudaEventRecord(ctx.eQ, s1);
    ln_bh<<<T_ * M_, 256, 0, s1>>>(qk2_h + D_, 2 * D_, kg_p, k2_h);                            // K2_ln
    cudaEventRecord(ctx.eK2, s1);
    cudaStreamWaitEvent(s1, ctx.e3, 0);
    gemm_h<<<gBig, 256, GSMEM, s1>>>(fpe_h, w_h + 4 * (size_t)NW, nullptr, nullptr, big1_h, D_); // Q2
    ln_bh<<<T_ * HW_, 256, 0, s1>>>(big1_h, D_, qg_p, q2_h);
    cudaEventRecord(ctx.eQ2, s1);

    // s2 (after Wc): V chain
    cudaStreamWaitEvent(s2, ctx.e3, 0);
    gemm_h<<<gBig, 256, GSMEM, s2>>>(feat_h, w_h + 3 * (size_t)NW, nullptr, nullptr, vb_h, D_);  // V
    cudaEventRecord(ctx.eV, s2);

    // stream 0 critical path
    cudaStreamWaitEvent(0, ctx.eW, 0);
    gemm_h<<<gBig, 256, GSMEM>>>(fp_h, w_h + 2 * (size_t)NW, nullptr, nullptr, big0_h, D_);      // K
    ln_bh<<<T_ * HW_, 256>>>(big0_h, D_, kg_s, kb_h);

    cudaStreamWaitEvent(0, ctx.eQ, 0);
    cudaStreamWaitEvent(0, ctx.eV, 0);
    flash_h<M_, HW_, true, false><<<dim3(M_ / 64, T_ * H_), 128, FSMEM>>>(
        qb_h, kb_h, vb_h, sh_h, tracks, fpos);

    // V2 = sh @ Wc^T
    cudaStreamWaitEvent(0, ctx.eWc, 0);
    gemm_h<<<gSm, 256, GSMEM>>>(sh_h, wc_h, nullptr, nullptr, v2_h, D_);

    cudaStreamWaitEvent(0, ctx.eQ2, 0);
    cudaStreamWaitEvent(0, ctx.eK2, 0);
    flash_h<HW_, M_, false, true><<<dim3(HW_ / 64, T_ * H_), 128, FSMEM>>>(
        q2_h, k2_h, v2_h, upd_h, fpos, tracks);

    gemm_h<<<gBig, 256, GSMEM>>>(upd_h, w_h + 6 * (size_t)NW, features, out, nullptr, D_);       // out
}

// round 11
// speedup vs baseline: 1.1799x; 1.1799x over previous
#include <cuda_runtime.h>
#include <cuda_bf16.h>
#include <math.h>
#include <stdint.h>

#define T_ 16
#define HW_ 1024
#define M_ 256
#define D_ 768
#define H_ 8
#define HD_ 96
#define SCALE_F 0.1020620726159658f  /* 1/sqrt(96) */

typedef __nv_bfloat16 bf16;
typedef __nv_bfloat162 bf162;

// ---------------- scratch (static device globals; no allocation) ----------------
__device__ __align__(256) bf16 h_feat[(size_t)T_ * HW_ * D_];
__device__ __align__(256) bf16 h_fp  [(size_t)T_ * HW_ * D_];   // featplus
__device__ __align__(256) bf16 h_fpe [(size_t)T_ * HW_ * D_];
__device__ __align__(256) bf16 h_kb  [(size_t)T_ * HW_ * D_];   // K_ln
__device__ __align__(256) bf16 h_vb  [(size_t)T_ * HW_ * D_];   // V
__device__ __align__(256) bf16 h_big0[(size_t)T_ * HW_ * D_];   // K pre-LN
__device__ __align__(256) bf16 h_big1[(size_t)T_ * HW_ * D_];   // Q2 pre-LN
__device__ __align__(256) bf16 h_q2  [(size_t)T_ * HW_ * D_];   // Q2_ln
__device__ __align__(256) bf16 h_upd [(size_t)T_ * HW_ * D_];   // flash2 out
__device__ __align__(256) bf16 h_tpe [(size_t)T_ * M_ * D_];
__device__ __align__(256) bf16 h_qb  [(size_t)T_ * M_ * D_];    // Q_ln
__device__ __align__(256) bf16 h_sm0 [(size_t)T_ * M_ * D_];    // Q pre-LN
__device__ __align__(256) bf16 h_sm1 [(size_t)T_ * M_ * D_];    // K2 pre-LN
__device__ __align__(256) bf16 h_k2  [(size_t)T_ * M_ * D_];    // K2_ln
__device__ __align__(256) bf16 h_sh  [(size_t)T_ * M_ * D_];    // sampled-heads
__device__ __align__(256) bf16 h_v2  [(size_t)T_ * M_ * D_];    // V2
__device__ __align__(256) bf16 h_W[8][D_ * D_];
__device__ __align__(256) bf16 h_wt [D_ * D_];                   // Wo_s^T (bf16)
__device__ __align__(256) bf16 h_wc [D_ * D_];                   // Wc = Wv_p @ Wo_s

// ---------------- ptx helpers ----------------
__device__ __forceinline__ unsigned cvta_s(const void* p) {
    return (unsigned)__cvta_generic_to_shared(p);
}
#define CP16(dst, src) asm volatile("cp.async.cg.shared.global [%0], [%1], 16;" :: "r"(dst), "l"(src))
#define CPC() asm volatile("cp.async.commit_group;")
#define CPW(n) asm volatile("cp.async.wait_group %0;" :: "n"(n))

__device__ __forceinline__ void ldsm4(unsigned a, unsigned& r0, unsigned& r1, unsigned& r2, unsigned& r3) {
    asm volatile("ldmatrix.sync.aligned.m8n8.x4.shared.b16 {%0,%1,%2,%3}, [%4];"
                 : "=r"(r0), "=r"(r1), "=r"(r2), "=r"(r3) : "r"(a));
}
__device__ __forceinline__ void ldsm4t(unsigned a, unsigned& r0, unsigned& r1, unsigned& r2, unsigned& r3) {
    asm volatile("ldmatrix.sync.aligned.m8n8.x4.trans.shared.b16 {%0,%1,%2,%3}, [%4];"
                 : "=r"(r0), "=r"(r1), "=r"(r2), "=r"(r3) : "r"(a));
}
__device__ __forceinline__ void mma_bf16(float* c,
    unsigned a0, unsigned a1, unsigned a2, unsigned a3, unsigned b0, unsigned b1) {
    asm volatile(
        "mma.sync.aligned.m16n8k16.row.col.f32.bf16.bf16.f32 "
        "{%0,%1,%2,%3},{%4,%5,%6,%7},{%8,%9},{%0,%1,%2,%3};"
        : "+f"(c[0]), "+f"(c[1]), "+f"(c[2]), "+f"(c[3])
        : "r"(a0), "r"(a1), "r"(a2), "r"(a3), "r"(b0), "r"(b1));
}
__device__ __forceinline__ unsigned packbf(float x, float y) {
    bf162 v = __floats2bfloat162_rn(x, y);
    return *reinterpret_cast<unsigned*>(&v);
}
// swizzled bf16-unit offset in a [rows][32] bf16 tile
__device__ __forceinline__ unsigned swz(int row, int g) {
    return ((row >> 1) << 6) | (((((row & 1) << 2) | g) ^ ((row >> 1) & 7)) << 3);
}

// ---------------- conversions ----------------
__global__ __launch_bounds__(256) void cvt3(const float* __restrict__ f, const float* __restrict__ pe,
                                            bf16* __restrict__ feat, bf16* __restrict__ fpeh,
                                            bf16* __restrict__ fph, int n4) {
    int i = blockIdx.x * 256 + threadIdx.x;
    if (i < n4) {
        float4 x = ((const float4*)f)[i];
        float4 y = ((const float4*)pe)[i];
        ((bf162*)feat)[2 * i]     = __floats2bfloat162_rn(x.x, x.y);
        ((bf162*)feat)[2 * i + 1] = __floats2bfloat162_rn(x.z, x.w);
        ((bf162*)fpeh)[2 * i]     = __floats2bfloat162_rn(y.x, y.y);
        ((bf162*)fpeh)[2 * i + 1] = __floats2bfloat162_rn(y.z, y.w);
        ((bf162*)fph)[2 * i]      = __floats2bfloat162_rn(x.x + y.x, x.y + y.y);
        ((bf162*)fph)[2 * i + 1]  = __floats2bfloat162_rn(x.z + y.z, x.w + y.w);
    }
}
__global__ __launch_bounds__(256) void cvt4(const float* __restrict__ s, bf16* __restrict__ d, int n4) {
    int i = blockIdx.x * 256 + threadIdx.x;
    if (i < n4) {
        float4 v = ((const float4*)s)[i];
        ((bf162*)d)[2 * i]     = __floats2bfloat162_rn(v.x, v.y);
        ((bf162*)d)[2 * i + 1] = __floats2bfloat162_rn(v.z, v.w);
    }
}
struct WP { const float* p[8]; };
__global__ __launch_bounds__(256) void cvtw(WP wp, bf16* __restrict__ dst) {
    int wi = blockIdx.y;
    const float* s = wp.p[wi];
    bf16* d = dst + (size_t)wi * (D_ * D_);
    int i = blockIdx.x * 256 + threadIdx.x;
    float4 v = ((const float4*)s)[i];
    ((bf162*)d)[2 * i]     = __floats2bfloat162_rn(v.x, v.y);
    ((bf162*)d)[2 * i + 1] = __floats2bfloat162_rn(v.z, v.w);
}
// transpose 768x768 fp32 -> bf16 (D[j,k] = S[k,j])
__global__ __launch_bounds__(256) void twt(const float* __restrict__ S, bf16* __restrict__ D) {
    __shared__ float tile[32][33];
    int bx = blockIdx.x * 32, by = blockIdx.y * 32;
    int tx = threadIdx.x & 31, ty = threadIdx.x >> 5;   // 32 x 8
#pragma unroll
    for (int i = 0; i < 32; i += 8)
        tile[ty + i][tx] = S[(size_t)(by + ty + i) * D_ + bx + tx];
    __syncthreads();
#pragma unroll
    for (int i = 0; i < 32; i += 8)
        D[(size_t)(bx + ty + i) * D_ + by + tx] = __float2bfloat16(tile[tx][ty + i]);
}

// ---------------- LayerNorm: bf16 in -> bf16 out ----------------
__global__ __launch_bounds__(256) void ln_bh(const bf16* __restrict__ X,
                                             const float* __restrict__ g, bf16* __restrict__ Y) {
    const bf16* row = X + (size_t)blockIdx.x * D_;
    bf16* orow = Y + (size_t)blockIdx.x * D_;
    int tid = threadIdx.x, lane = tid & 31, w = tid >> 5;
    float v0 = __bfloat162float(row[tid]);
    float v1 = __bfloat162float(row[tid + 256]);
    float v2 = __bfloat162float(row[tid + 512]);
    float s = v0 + v1 + v2;
    float q = v0 * v0 + v1 * v1 + v2 * v2;
#pragma unroll
    for (int o = 16; o; o >>= 1) {
        s += __shfl_xor_sync(~0u, s, o);
        q += __shfl_xor_sync(~0u, q, o);
    }
    __shared__ float ps[8], pq[8], bc[2];
    if (lane == 0) { ps[w] = s; pq[w] = q; }
    __syncthreads();
    if (tid == 0) {
        float ts = 0.0f, tq = 0.0f;
#pragma unroll
        for (int i = 0; i < 8; i++) { ts += ps[i]; tq += pq[i]; }
        float mean = ts * (1.0f / 768.0f);
        float var = tq * (1.0f / 768.0f) - mean * mean;
        bc[0] = mean;
        bc[1] = rsqrtf(var + 1e-6f);
    }
    __syncthreads();
    float mean = bc[0], inv = bc[1];
    orow[tid]       = __float2bfloat16((v0 - mean) * inv * g[tid]);
    orow[tid + 256] = __float2bfloat16((v1 - mean) * inv * g[tid + 256]);
    orow[tid + 512] = __float2bfloat16((v2 - mean) * inv * g[tid + 512]);
}

// ---------------- dense GEMM: C[R,768] = A[R,768] @ W[768,768]^T ----------------
// 3-stage cp.async pipeline, one barrier per k-step (R5/R9 proven).
__global__ __launch_bounds__(256) void gemm_h(
    const bf16* __restrict__ A, const bf16* __restrict__ W,
    const float* __restrict__ addsrc, float* __restrict__ Cf, bf16* __restrict__ Ch)
{
    extern __shared__ bf16 sm[];          // 3 stages x (A 8KB | W 8KB)
    const int tid = threadIdx.x, lane = tid & 31, warp = tid >> 5;
    const int wm = warp & 3, wn = warp >> 2;
    const int bm = blockIdx.y * 128, bn = blockIdx.x * 128;
    const unsigned base = cvta_s(sm);
    const int r0 = tid >> 2, r1 = r0 + 64, gg = tid & 3;
    const bf16* As0 = A + (size_t)(bm + r0) * D_ + gg * 8;
    const bf16* As1 = A + (size_t)(bm + r1) * D_ + gg * 8;
    const bf16* Ws0 = W + (size_t)(bn + r0) * D_ + gg * 8;
    const bf16* Ws1 = W + (size_t)(bn + r1) * D_ + gg * 8;
    const unsigned dA0 = base + (swz(r0, gg) << 1), dA1 = base + (swz(r1, gg) << 1);
    const unsigned dW0 = base + 8192 + (swz(r0, gg) << 1), dW1 = base + 8192 + (swz(r1, gg) << 1);

    float c[2][8][4] = {};

#pragma unroll
    for (int s = 0; s < 2; s++) {
        unsigned o = s * 16384u;
        int k0 = s * 32;
        CP16(dA0 + o, As0 + k0); CP16(dA1 + o, As1 + k0);
        CP16(dW0 + o, Ws0 + k0); CP16(dW1 + o, Ws1 + k0);
        CPC();
    }

    const int ITERS = D_ / 32;  // 24
    const int rlow = lane & 15, khalf = lane >> 4;
    for (int it = 0; it < ITERS; ++it) {
        CPW(1);
        __syncthreads();
        if (it + 2 < ITERS) {
            int k0 = (it + 2) * 32;
            unsigned o = (unsigned)((it + 2) % 3) * 16384u;
            CP16(dA0 + o, As0 + k0); CP16(dA1 + o, As1 + k0);
            CP16(dW0 + o, Ws0 + k0); CP16(dW1 + o, Ws1 + k0);
        }
        CPC();
        unsigned so = (unsigned)(it % 3) * 16384u;
        unsigned ab = base + so, wb = base + 8192 + so;
#pragma unroll
        for (int kk = 0; kk < 32; kk += 16) {
            int g = (kk >> 3) + khalf;
            unsigned a[2][4], bfr[4][4];
#pragma unroll
            for (int mt = 0; mt < 2; mt++) {
                int row = wm * 32 + mt * 16 + rlow;
                ldsm4(ab + (swz(row, g) << 1), a[mt][0], a[mt][1], a[mt][2], a[mt][3]);
            }
#pragma unroll
            for (int bt = 0; bt < 4; bt++) {
                int row = wn * 64 + bt * 16 + rlow;
                ldsm4(wb + (swz(row, g) << 1), bfr[bt][0], bfr[bt][1], bfr[bt][2], bfr[bt][3]);
            }
#pragma unroll
            for (int mt = 0; mt < 2; mt++)
#pragma unroll
                for (int nt = 0; nt < 8; nt++) {
                    int bt = nt >> 1, hi = nt & 1;
                    mma_bf16(c[mt][nt], a[mt][0], a[mt][1], a[mt][2], a[mt][3],
                             bfr[bt][hi ? 1 : 0], bfr[bt][hi ? 3 : 2]);
                }
        }
    }

    const int ml = lane >> 2, nl = 2 * (lane & 3);
#pragma unroll
    for (int mt = 0; mt < 2; mt++) {
        int m0 = bm + wm * 32 + mt * 16 + ml;
#pragma unroll
        for (int nt = 0; nt < 8; nt++) {
            int n0 = bn + wn * 64 + nt * 8 + nl;
            size_t o0 = (size_t)m0 * D_ + n0, o1 = o0 + (size_t)8 * D_;
            float x0 = c[mt][nt][0], x1 = c[mt][nt][1];
            float y0 = c[mt][nt][2], y1 = c[mt][nt][3];
            if (addsrc) {
                float2 s0 = *(const float2*)(addsrc + o0);
                float2 s1 = *(const float2*)(addsrc + o1);
                x0 += s0.x; x1 += s0.y; y0 += s1.x; y1 += s1.y;
            }
            if (Cf) {
                *(float2*)(Cf + o0) = make_float2(x0, x1);
                *(float2*)(Cf + o1) = make_float2(y0, y1);
            }
            if (Ch) {
                *(bf162*)(Ch + o0) = __floats2bfloat162_rn(x0, x1);
                *(bf162*)(Ch + o1) = __floats2bfloat162_rn(y0, y1);
            }
        }
    }
}

// ---------------- fused flash attention (R5 proven, unchanged) ----------------
template<int MQ, int KN, bool QPT, bool KPT>
__global__ __launch_bounds__(128) void flash_h(
    const bf16* __restrict__ Q, const bf16* __restrict__ K,
    const bf16* __restrict__ V, bf16* __restrict__ O,
    const float* __restrict__ qpos, const float* __restrict__ kpos)
{
    constexpr int ITERS = KN / 64;
    extern __shared__ char smem[];
    unsigned qU  = cvta_s(smem);
    unsigned kU  = qU + 12288;
    unsigned vU  = qU + 36864;
    unsigned kpU = qU + 63488;
    float2* sKP = (float2*)(smem + 63488);

    const int z = blockIdx.y, t = z >> 3, h = z & 7;
    const int bm = blockIdx.x * 64;
    const bf16* Qb = Q + (size_t)t * MQ * D_ + h * HD_;
    const bf16* Kb = K + (size_t)t * KN * D_ + h * HD_;
    const bf16* Vb = V + (size_t)t * KN * D_ + h * HD_;
    bf16* Ob = O + (size_t)t * MQ * D_ + h * HD_;
    const float* qp = qpos + (QPT ? (size_t)t * MQ * 2 : 0);
    const float* kp = kpos + (KPT ? (size_t)t * KN * 2 : 0);

    const int tid = threadIdx.x, lane = tid & 31, w = tid >> 5;
    const int gq = lane >> 2, tg = lane & 3;
    const int rlow = lane & 15, khalf = lane >> 4;

    int lrow[6], lg[6];
    unsigned kdst[6], vdst[6];
    size_t soff[6];
#pragma unroll
    for (int i = 0; i < 6; i++) {
        int idx = tid + i * 128;
        lrow[i] = idx / 12; lg[i] = idx % 12;
        kdst[i] = ((lg[i] >> 2) * 4096) + (swz(lrow[i], lg[i] & 3) << 1);
        vdst[i] = lrow[i] * 208 + lg[i] * 16;
        soff[i] = (size_t)lrow[i] * D_ + lg[i] * 8;
    }

#pragma unroll
    for (int i = 0; i < 6; i++) {
        CP16(qU + kdst[i], Qb + (size_t)bm * D_ + soff[i]);
        CP16(kU + kdst[i], Kb + soff[i]);
        CP16(vU + vdst[i], Vb + soff[i]);
    }
    if (tid < 32) CP16(kpU + tid * 16, (const char*)kp + tid * 16);
    CPC();

    float2 q0 = *(const float2*)(qp + 2 * (bm + w * 16 + gq));
    float2 q1 = *(const float2*)(qp + 2 * (bm + w * 16 + gq + 8));

    float m0 = -1e30f, m1 = -1e30f, l0 = 0.0f, l1 = 0.0f;
    float o[12][4] = {};
    unsigned qa[6][4];

    for (int it = 0; it < ITERS; ++it) {
        int buf = it & 1;
        if (it + 1 < ITERS) {
            int kb = (it + 1) * 64;
            unsigned ok = (buf ^ 1) * 12288u, ov = (buf ^ 1) * 13312u;
            size_t sb = (size_t)kb * D_;
#pragma unroll
            for (int i = 0; i < 6; i++) {
                CP16(kU + ok + kdst[i], Kb + sb + soff[i]);
                CP16(vU + ov + vdst[i], Vb + sb + soff[i]);
            }
            if (tid < 32) CP16(kpU + (buf ^ 1) * 512 + tid * 16, (const char*)kp + (size_t)kb * 8 + tid * 16);
            CPC(); CPW(1);
        } else CPW(0);
        __syncthreads();

        if (it == 0) {
#pragma unroll
            for (int ks = 0; ks < 6; ks++) {
                int kc = ks >> 1, g = ((ks & 1) << 1) + khalf;
                ldsm4(qU + kc * 4096 + (swz(w * 16 + rlow, g) << 1),
                      qa[ks][0], qa[ks][1], qa[ks][2], qa[ks][3]);
            }
        }

        unsigned kbase = kU + buf * 12288u, vbase = vU + buf * 13312u;
        float2* kpb = sKP + buf * 64;

        float s[8][4] = {};
#pragma unroll
        for (int ks = 0; ks < 6; ks++) {
            int kc = ks >> 1, g = ((ks & 1) << 1) + khalf;
            unsigned bfr[4][4];
#pragma unroll
            for (int rg = 0; rg < 4; rg++)
                ldsm4(kbase + kc * 4096 + (swz(rg * 16 + rlow, g) << 1),
                      bfr[rg][0], bfr[rg][1], bfr[rg][2], bfr[rg][3]);
#pragma unroll
            for (int rg = 0; rg < 4; rg++) {
                mma_bf16(s[2 * rg],     qa[ks][0], qa[ks][1], qa[ks][2], qa[ks][3], bfr[rg][0], bfr[rg][2]);
                mma_bf16(s[2 * rg + 1], qa[ks][0], qa[ks][1], qa[ks][2], qa[ks][3], bfr[rg][1], bfr[rg][3]);
            }
        }

        float rm0 = -1e30f, rm1 = -1e30f;
#pragma unroll
        for (int j = 0; j < 8; j++) {
            float2 kp0 = kpb[8 * j + 2 * tg];
            float2 kp1 = kpb[8 * j + 2 * tg + 1];
            float dx, dy;
            dx = q0.x - kp0.x; dy = q0.y - kp0.y;
            s[j][0] = s[j][0] * SCALE_F - 2.0f * (dx * dx + dy * dy);
            dx = q0.x - kp1.x; dy = q0.y - kp1.y;
            s[j][1] = s[j][1] * SCALE_F - 2.0f * (dx * dx + dy * dy);
            dx = q1.x - kp0.x; dy = q1.y - kp0.y;
            s[j][2] = s[j][2] * SCALE_F - 2.0f * (dx * dx + dy * dy);
            dx = q1.x - kp1.x; dy = q1.y - kp1.y;
            s[j][3] = s[j][3] * SCALE_F - 2.0f * (dx * dx + dy * dy);
            rm0 = fmaxf(rm0, fmaxf(s[j][0], s[j][1]));
            rm1 = fmaxf(rm1, fmaxf(s[j][2], s[j][3]));
        }
        rm0 = fmaxf(rm0, __shfl_xor_sync(~0u, rm0, 1));
        rm0 = fmaxf(rm0, __shfl_xor_sync(~0u, rm0, 2));
        rm1 = fmaxf(rm1, __shfl_xor_sync(~0u, rm1, 1));
        rm1 = fmaxf(rm1, __shfl_xor_sync(~0u, rm1, 2));

        float m0n = fmaxf(m0, rm0), m1n = fmaxf(m1, rm1);
        float sc0 = __expf(m0 - m0n), sc1 = __expf(m1 - m1n);
        m0 = m0n; m1 = m1n;
        l0 *= sc0; l1 *= sc1;
#pragma unroll
        for (int j = 0; j < 8; j++) {
            s[j][0] = __expf(s[j][0] - m0n);
            s[j][1] = __expf(s[j][1] - m0n);
            s[j][2] = __expf(s[j][2] - m1n);
            s[j][3] = __expf(s[j][3] - m1n);
            l0 += s[j][0] + s[j][1];
            l1 += s[j][2] + s[j][3];
        }
#pragma unroll
        for (int nt = 0; nt < 12; nt++) {
            o[nt][0] *= sc0; o[nt][1] *= sc0;
            o[nt][2] *= sc1; o[nt][3] *= sc1;
        }

        unsigned pa[4][4];
#pragma unroll
        for (int kk = 0; kk < 4; kk++) {
            pa[kk][0] = packbf(s[2 * kk][0],     s[2 * kk][1]);
            pa[kk][1] = packbf(s[2 * kk][2],     s[2 * kk][3]);
            pa[kk][2] = packbf(s[2 * kk + 1][0], s[2 * kk + 1][1]);
            pa[kk][3] = packbf(s[2 * kk + 1][2], s[2 * kk + 1][3]);
        }

#pragma unroll
        for (int kk = 0; kk < 4; kk++) {
#pragma unroll
            for (int p = 0; p < 6; p++) {
                unsigned baddr = vbase + (kk * 16 + rlow) * 208 + (p * 16 + khalf * 8) * 2;
                unsigned b0, b1, b2, b3;
                ldsm4t(baddr, b0, b1, b2, b3);
                mma_bf16(o[2 * p],     pa[kk][0], pa[kk][1], pa[kk][2], pa[kk][3], b0, b1);
                mma_bf16(o[2 * p + 1], pa[kk][0], pa[kk][1], pa[kk][2], pa[kk][3], b2, b3);
            }
        }
        __syncthreads();
    }

    l0 += __shfl_xor_sync(~0u, l0, 1); l0 += __shfl_xor_sync(~0u, l0, 2);
    l1 += __shfl_xor_sync(~0u, l1, 1); l1 += __shfl_xor_sync(~0u, l1, 2);
    float inv0 = 1.0f / l0, inv1 = 1.0f / l1;

    int mrow = bm + w * 16 + gq;
#pragma unroll
    for (int nt = 0; nt < 12; nt++) {
        int n0 = nt * 8 + 2 * tg;
        *(bf162*)(Ob + (size_t)mrow * D_ + n0) =
            __floats2bfloat162_rn(o[nt][0] * inv0, o[nt][1] * inv0);
        *(bf162*)(Ob + (size_t)(mrow + 8) * D_ + n0) =
            __floats2bfloat162_rn(o[nt][2] * inv1, o[nt][3] * inv1);
    }
}

// ---------------- persistent stream/event handles (created once, reused) --------
struct Ctx {
    cudaStream_t s1, s2;
    cudaEvent_t eStart, eW, e3, e4, eQ, eQ2, eV, eK2, eWc, eK, eJoin;
    Ctx() {
        cudaStreamCreateWithFlags(&s1, cudaStreamNonBlocking);
        cudaStreamCreateWithFlags(&s2, cudaStreamNonBlocking);
        cudaEventCreateWithFlags(&eStart, cudaEventDisableTiming);
        cudaEventCreateWithFlags(&eW, cudaEventDisableTiming);
        cudaEventCreateWithFlags(&e3, cudaEventDisableTiming);
        cudaEventCreateWithFlags(&e4, cudaEventDisableTiming);
        cudaEventCreateWithFlags(&eQ, cudaEventDisableTiming);
        cudaEventCreateWithFlags(&eQ2, cudaEventDisableTiming);
        cudaEventCreateWithFlags(&eV, cudaEventDisableTiming);
        cudaEventCreateWithFlags(&eK2, cudaEventDisableTiming);
        cudaEventCreateWithFlags(&eWc, cudaEventDisableTiming);
        cudaEventCreateWithFlags(&eK, cudaEventDisableTiming);
        cudaEventCreateWithFlags(&eJoin, cudaEventDisableTiming);
    }
};

// =================================================================================
extern "C" void kernel_launch(void* const* d_in, const int* in_sizes, int n_in,
                              void* d_out, int out_size)
{
    static Ctx ctx;   // one-time creation on first call (pre-baseline)

    const float* features = (const float*)d_in[0];
    const float* tracks   = (const float*)d_in[1];
    const float* fpos     = (const float*)d_in[2];
    const float* tpe      = (const float*)d_in[3];
    const float* fpe      = (const float*)d_in[4];
    WP wp;
    wp.p[0] = (const float*)d_in[5];   // Wq_s
    wp.p[1] = (const float*)d_in[6];   // Wk_s
    wp.p[2] = (const float*)d_in[7];   // Wv_s
    wp.p[3] = (const float*)d_in[10];  // Wo_s
    wp.p[4] = (const float*)d_in[11];  // Wq_p
    wp.p[5] = (const float*)d_in[12];  // Wk_p
    wp.p[6] = (const float*)d_in[13];  // Wv_p
    wp.p[7] = (const float*)d_in[16];  // Wout_p
    const float* qg_s = (const float*)d_in[8];
    const float* kg_s = (const float*)d_in[9];
    const float* qg_p = (const float*)d_in[14];
    const float* kg_p = (const float*)d_in[15];
    float* out = (float*)d_out;

    bf16 *feat_h, *fp_h, *fpe_h, *kb_h, *vb_h, *big0_h, *big1_h, *q2_h, *upd_h;
    bf16 *tpe_h, *qb_h, *sm0_h, *sm1_h, *k2_h, *sh_h, *v2_h, *w_h, *wt_h, *wc_h;
    cudaGetSymbolAddress((void**)&feat_h, h_feat);
    cudaGetSymbolAddress((void**)&fp_h,   h_fp);
    cudaGetSymbolAddress((void**)&fpe_h,  h_fpe);
    cudaGetSymbolAddress((void**)&kb_h,   h_kb);
    cudaGetSymbolAddress((void**)&vb_h,   h_vb);
    cudaGetSymbolAddress((void**)&big0_h, h_big0);
    cudaGetSymbolAddress((void**)&big1_h, h_big1);
    cudaGetSymbolAddress((void**)&q2_h,   h_q2);
    cudaGetSymbolAddress((void**)&upd_h,  h_upd);
    cudaGetSymbolAddress((void**)&tpe_h,  h_tpe);
    cudaGetSymbolAddress((void**)&qb_h,   h_qb);
    cudaGetSymbolAddress((void**)&sm0_h,  h_sm0);
    cudaGetSymbolAddress((void**)&sm1_h,  h_sm1);
    cudaGetSymbolAddress((void**)&k2_h,   h_k2);
    cudaGetSymbolAddress((void**)&sh_h,   h_sh);
    cudaGetSymbolAddress((void**)&v2_h,   h_v2);
    cudaGetSymbolAddress((void**)&w_h,    h_W);
    cudaGetSymbolAddress((void**)&wt_h,   h_wt);
    cudaGetSymbolAddress((void**)&wc_h,   h_wc);

    const int NBIG = T_ * HW_ * D_;  // 12,582,912
    const int NSM  = T_ * M_ * D_;   // 3,145,728
    const int NW   = D_ * D_;        // 589,824

    const int GSMEM = 49152;
    cudaFuncSetAttribute(gemm_h, cudaFuncAttributeMaxDynamicSharedMemorySize, GSMEM);
    const int FSMEM = 64512;
    cudaFuncSetAttribute(flash_h<M_, HW_, true, false>,
                         cudaFuncAttributeMaxDynamicSharedMemorySize, FSMEM);
    cudaFuncSetAttribute(flash_h<HW_, M_, false, true>,
                         cudaFuncAttributeMaxDynamicSharedMemorySize, FSMEM);

    cudaStream_t s1 = ctx.s1, s2 = ctx.s2;

    dim3 gBig(6, 128);     // full big GEMM (M=16384)
    dim3 gBigH(6, 64);     // half big GEMM (M=8192)
    dim3 gSm(6, 32);       // full small GEMM
    dim3 gSmH(6, 16);      // half small GEMM
    dim3 gW(6, 6);

    // half offsets (t0 = 8)
    const size_t oBig = (size_t)8 * HW_ * D_;   // rows offset in big tensors
    const size_t oSm  = (size_t)8 * M_ * D_;    // rows offset in small tensors
    const size_t oTrk = (size_t)8 * M_ * 2;     // tracks offset

    // fork s1/s2 from the capturing (legacy) stream
    cudaEventRecord(ctx.eStart, 0);
    cudaStreamWaitEvent(s1, ctx.eStart, 0);
    cudaStreamWaitEvent(s2, ctx.eStart, 0);

    // s2: weight conversion, WoT transpose, Wc = Wv_p @ Wo_s, then V chain + K2 chain
    cvtw<<<dim3(NW / 1024, 8), 256, 0, s2>>>(wp, w_h);
    cudaEventRecord(ctx.eW, s2);
    twt<<<dim3(24, 24), 256, 0, s2>>>(wp.p[3], wt_h);                                          // Wo_s^T
    gemm_h<<<gW, 256, GSMEM, s2>>>(w_h + 6 * (size_t)NW, wt_h, nullptr, nullptr, wc_h);        // Wc
    cudaEventRecord(ctx.eWc, s2);

    // stream 0: big conversions + K chain (critical path)
    cvt3<<<NBIG / 1024, 256>>>(features, fpe, feat_h, fpe_h, fp_h, NBIG / 4);
    cudaEventRecord(ctx.e3, 0);

    // s1: tpe conversion, Q chain, then Q2 chain
    cvt4<<<NSM / 1024, 256, 0, s1>>>(tpe, tpe_h, NSM / 4);
    cudaEventRecord(ctx.e4, s1);
    cudaStreamWaitEvent(s1, ctx.eW, 0);
    gemm_h<<<gSm, 256, GSMEM, s1>>>(tpe_h, w_h + 0 * (size_t)NW, nullptr, nullptr, sm0_h);     // Q
    ln_bh<<<T_ * M_, 256, 0, s1>>>(sm0_h, qg_s, qb_h);
    cudaEventRecord(ctx.eQ, s1);
    cudaStreamWaitEvent(s1, ctx.e3, 0);
    gemm_h<<<gBig, 256, GSMEM, s1>>>(fpe_h, w_h + 4 * (size_t)NW, nullptr, nullptr, big1_h);   // Q2
    ln_bh<<<T_ * HW_, 256, 0, s1>>>(big1_h, qg_p, q2_h);
    cudaEventRecord(ctx.eQ2, s1);

    // s2 (after Wc): V chain, then K2 chain
    cudaStreamWaitEvent(s2, ctx.e3, 0);
    gemm_h<<<gBig, 256, GSMEM, s2>>>(feat_h, w_h + 2 * (size_t)NW, nullptr, nullptr, vb_h);    // V
    cudaEventRecord(ctx.eV, s2);
    cudaStreamWaitEvent(s2, ctx.e4, 0);
    gemm_h<<<gSm, 256, GSMEM, s2>>>(tpe_h, w_h + 5 * (size_t)NW, nullptr, nullptr, sm1_h);     // K2
    ln_bh<<<T_ * M_, 256, 0, s2>>>(sm1_h, kg_p, k2_h);
    cudaEventRecord(ctx.eK2, s2);

    // stream 0 critical path
    cudaStreamWaitEvent(0, ctx.eW, 0);
    gemm_h<<<gBig, 256, GSMEM>>>(fp_h, w_h + 1 * (size_t)NW, nullptr, nullptr, big0_h);        // K
    ln_bh<<<T_ * HW_, 256>>>(big0_h, kg_s, kb_h);
    cudaEventRecord(ctx.eK, 0);

    // ================= tail: split by t-halves across stream0 (A: t 0-7) and s1 (B: t 8-15)
    // half A on stream 0
    cudaStreamWaitEvent(0, ctx.eQ, 0);
    cudaStreamWaitEvent(0, ctx.eV, 0);
    flash_h<M_, HW_, true, false><<<dim3(M_ / 64, 8 * H_), 128, FSMEM>>>(
        qb_h, kb_h, vb_h, sh_h, tracks, fpos);
    cudaStreamWaitEvent(0, ctx.eWc, 0);
    gemm_h<<<gSmH, 256, GSMEM>>>(sh_h, wc_h, nullptr, nullptr, v2_h);                          // V2 (A)
    cudaStreamWaitEvent(0, ctx.eQ2, 0);
    cudaStreamWaitEvent(0, ctx.eK2, 0);
    flash_h<HW_, M_, false, true><<<dim3(HW_ / 64, 8 * H_), 128, FSMEM>>>(
        q2_h, k2_h, v2_h, upd_h, fpos, tracks);
    gemm_h<<<gBigH, 256, GSMEM>>>(upd_h, w_h + 7 * (size_t)NW, features, out, nullptr);        // out (A)

    // half B on s1 (s1 is already past Q2 chain in-order; q2 ready in-stream)
    cudaStreamWaitEvent(s1, ctx.eK, 0);
    cudaStreamWaitEvent(s1, ctx.eV, 0);
    flash_h<M_, HW_, true, false><<<dim3(M_ / 64, 8 * H_), 128, FSMEM, s1>>>(
        qb_h + oSm, kb_h + oBig, vb_h + oBig, sh_h + oSm, tracks + oTrk, fpos);
    cudaStreamWaitEvent(s1, ctx.eWc, 0);
    gemm_h<<<gSmH, 256, GSMEM, s1>>>(sh_h + oSm, wc_h, nullptr, nullptr, v2_h + oSm);          // V2 (B)
    cudaStreamWaitEvent(s1, ctx.eK2, 0);
    flash_h<HW_, M_, false, true><<<dim3(HW_ / 64, 8 * H_), 128, FSMEM, s1>>>(
        q2_h + oBig, k2_h + oSm, v2_h + oSm, upd_h + oBig, fpos, tracks + oTrk);
    gemm_h<<<gBigH, 256, GSMEM, s1>>>(upd_h + oBig, w_h + 7 * (size_t)NW,
                                      features + oBig, out + oBig, nullptr);                   // out (B)
    cudaEventRecord(ctx.eJoin, s1);

    // join half B back into the capturing stream
    cudaStreamWaitEvent(0, ctx.eJoin, 0);
}